// round 8
// baseline (speedup 1.0000x reference)
#include <cuda_runtime.h>
#include <cstdint>

#define N_B 8
#define NQ  1024
#define NK  1024
#define DD  1024
#define HH  16
#define DH  64
#define ELEMS (N_B*NQ*DD)   // 8388608

// Scratch. g_q: tf32 bits, pre-scaled by 1/8, [bh][row][e].
// g_k: tf32, [bh][key][e]. g_v: tf32, TRANSPOSED+PERMUTED [bh][e][permk(key)].
__device__ float g_q[HH*N_B*NQ*DH];
__device__ float g_k[HH*N_B*NK*DH];
__device__ float g_v[HH*N_B*NK*DH];
__device__ float g_o[N_B*NQ*DD];
// tf32-pre-rounded copies of GEMM inputs
__device__ float g_ar[ELEMS];
__device__ float g_br[ELEMS];
__device__ float g_cr[ELEMS];
__device__ float g_wr[4][DD*DD];

__device__ __forceinline__ uint32_t f2tf(float x) {
    uint32_t u; asm("cvt.rna.tf32.f32 %0, %1;" : "=r"(u) : "f"(x)); return u;
}

__device__ __forceinline__ void mma8(float* c, const uint32_t* a, const uint32_t* b) {
    asm volatile(
        "mma.sync.aligned.m16n8k8.row.col.f32.tf32.tf32.f32 "
        "{%0,%1,%2,%3}, {%4,%5,%6,%7}, {%8,%9}, {%0,%1,%2,%3};"
        : "+f"(c[0]), "+f"(c[1]), "+f"(c[2]), "+f"(c[3])
        : "r"(a[0]), "r"(a[1]), "r"(a[2]), "r"(a[3]), "r"(b[0]), "r"(b[1]));
}

__device__ __forceinline__ void ldsm4(uint32_t* d, uint32_t addr) {
    asm volatile("ldmatrix.sync.aligned.m8n8.x4.shared.b16 {%0,%1,%2,%3}, [%4];"
        : "=r"(d[0]), "=r"(d[1]), "=r"(d[2]), "=r"(d[3]) : "r"(addr));
}

__device__ __forceinline__ uint32_t s2u(const void* p) {
    return (uint32_t)__cvta_generic_to_shared(p);
}

__device__ __forceinline__ void cpa16(uint32_t dst, const void* src) {
    asm volatile("cp.async.cg.shared.global [%0], [%1], 16;" :: "r"(dst), "l"(src));
}
#define CPA_COMMIT asm volatile("cp.async.commit_group;")
#define CPA_WAIT0  asm volatile("cp.async.wait_group 0;")

__device__ __forceinline__ void pref_l2(const void* p) {
    asm volatile("prefetch.global.L2 [%0];" :: "l"(p));
}

// ---------------------------------------------------------------------------
// Fused pre-round: all 3 activations + 4 weights in one grid-stride launch
// ---------------------------------------------------------------------------
#define ACT4 (ELEMS/4)
#define W4   (DD*DD/4)
#define TOT4 (3*ACT4 + 4*W4)

__global__ __launch_bounds__(256) void round_all(
    const float4* __restrict__ q, const float4* __restrict__ k,
    const float4* __restrict__ v, const float4* __restrict__ wq,
    const float4* __restrict__ wk, const float4* __restrict__ wv,
    const float4* __restrict__ wo,
    float4* __restrict__ ar, float4* __restrict__ br, float4* __restrict__ cr,
    float4* __restrict__ wr)
{
    int i = blockIdx.x * blockDim.x + threadIdx.x;
    int stride = gridDim.x * blockDim.x;
    for (; i < TOT4; i += stride) {
        const float4* src; float4* dst; int j;
        if (i < 3 * ACT4) {
            int r = i / ACT4; j = i - r * ACT4;
            src = (r == 0) ? q : (r == 1) ? k : v;
            dst = (r == 0) ? ar : (r == 1) ? br : cr;
        } else {
            int t = i - 3 * ACT4;
            int r = t / W4; j = t - r * W4;
            src = (r == 0) ? wq : (r == 1) ? wk : (r == 2) ? wv : wo;
            dst = wr + r * W4;
        }
        float4 x = src[j];
        *(uint4*)(dst + j) = make_uint4(f2tf(x.x), f2tf(x.y), f2tf(x.z), f2tf(x.w));
    }
}

// ---------------------------------------------------------------------------
// GEMM core: C[m, r] = sum_d A[m,d] * W[r,d]  (tf32 mma, inputs pre-rounded)
// 32-k-col stages, 2 smem buffers, ONE __syncthreads per stage,
// register-level double buffering of A fragments (volatile asm => manual sched).
// ---------------------------------------------------------------------------
#define GP2 36

__device__ __forceinline__ void gemm_body(
    const float* __restrict__ A, const float* __restrict__ W,
    float* __restrict__ out, int mode, int bx, int by, float* As0, float* Bs0)
{
    float (*As)[128 * GP2] = (float(*)[128 * GP2])As0;
    float (*Bs)[128 * GP2] = (float(*)[128 * GP2])Bs0;
    const int tid  = threadIdx.x;
    const int lane = tid & 31, warp = tid >> 5;
    const int wm = warp >> 2, wn = warp & 3;
    const int m0 = by * 128, n0 = bx * 128;

    float c[4][4][4];
#pragma unroll
    for (int a = 0; a < 4; a++)
#pragma unroll
        for (int b = 0; b < 4; b++)
#pragma unroll
            for (int i = 0; i < 4; i++) c[a][b][i] = 0.f;

    const int a_off = (wm * 64 + (lane & 15)) * GP2 + 4 * (lane >> 4);
    const int b_off = (wn * 32 + ((lane >> 4) * 8) + (lane & 7)) * GP2 + 4 * ((lane >> 3) & 1);

    auto stage = [&](int t, int s) {
#pragma unroll
        for (int i = 0; i < 4; i++) {
            int ch = tid + i * 256;
            int row = ch >> 3, col = (ch & 7) * 4;
            cpa16(s2u(As[s] + row * GP2 + col), A + (size_t)(m0 + row) * DD + t * 32 + col);
            cpa16(s2u(Bs[s] + row * GP2 + col), W + (size_t)(n0 + row) * DD + t * 32 + col);
        }
        CPA_COMMIT;
    };

    stage(0, 0);

    uint32_t af0[4][4], af1[4][4];

    for (int kt = 0; kt < 32; kt++) {
        CPA_WAIT0;
        __syncthreads();
        if (kt + 1 < 32) stage(kt + 1, (kt + 1) & 1);

        const int s = kt & 1;
        // prime A fragments for kk=0
#pragma unroll
        for (int mt = 0; mt < 4; mt++)
            ldsm4(af0[mt], s2u(As[s] + a_off + mt * 16 * GP2 + 0));

#pragma unroll
        for (int kk = 0; kk < 4; kk++) {
            uint32_t (*a)[4]  = (kk & 1) ? af1 : af0;
            uint32_t (*an)[4] = (kk & 1) ? af0 : af1;
            uint32_t bf0[4], bf1[4];
            // issue bf(ntp0), then prefetch next kk's af, then mma ntp0
            ldsm4(bf0, s2u(Bs[s] + b_off + 0 * 16 * GP2 + kk * 8));
            if (kk < 3) {
#pragma unroll
                for (int mt = 0; mt < 4; mt++)
                    ldsm4(an[mt], s2u(As[s] + a_off + mt * 16 * GP2 + (kk + 1) * 8));
            }
            ldsm4(bf1, s2u(Bs[s] + b_off + 1 * 16 * GP2 + kk * 8));
#pragma unroll
            for (int mt = 0; mt < 4; mt++) {
                mma8(c[mt][0], a[mt], &bf0[0]);
                mma8(c[mt][1], a[mt], &bf0[2]);
            }
#pragma unroll
            for (int mt = 0; mt < 4; mt++) {
                mma8(c[mt][2], a[mt], &bf1[0]);
                mma8(c[mt][3], a[mt], &bf1[2]);
            }
        }
    }

#pragma unroll
    for (int mt = 0; mt < 4; mt++) {
        int mr = m0 + wm * 64 + mt * 16 + (lane >> 2);
#pragma unroll
        for (int nt = 0; nt < 4; nt++) {
            int nc = n0 + wn * 32 + nt * 8 + 2 * (lane & 3);
#pragma unroll
            for (int half = 0; half < 2; half++) {
                int m = mr + half * 8;
                float v0 = c[mt][nt][half * 2 + 0];
                float v1 = c[mt][nt][half * 2 + 1];
                if (mode == 1) {
                    *(float2*)(out + (size_t)m * DD + nc) = make_float2(v0, v1);
                } else if (mode == 0 || mode == 2) {
                    float sc = (mode == 0) ? 0.125f : 1.0f;
                    size_t idx = ((size_t)((nc >> 6) * N_B + (m >> 10)) << 16)
                               + (size_t)((m & 1023) * 64 + (nc & 63));
                    float2 w = make_float2(__uint_as_float(f2tf(v0 * sc)),
                                           __uint_as_float(f2tf(v1 * sc)));
                    *(float2*)(out + idx) = w;
                } else {
                    int key = m & 1023, n = m >> 10;
                    int lk = key & 7;
                    int kp = (key & ~7) | ((lk & 1) ? 4 + (lk >> 1) : (lk >> 1));
#pragma unroll
                    for (int cc = 0; cc < 2; cc++) {
                        int r = nc + cc, h = r >> 6, e = r & 63;
                        size_t idx = ((size_t)(h * N_B + n) << 16) + (size_t)e * NK + kp;
                        out[idx] = __uint_as_float(f2tf(cc ? v1 : v0));
                    }
                }
            }
        }
    }
}

__global__ __launch_bounds__(256, 2) void gemm_qkv(
    const float* __restrict__ Aq, const float* __restrict__ Ak, const float* __restrict__ Av,
    const float* __restrict__ Wq, const float* __restrict__ Wk, const float* __restrict__ Wv,
    float* __restrict__ oq, float* __restrict__ ok, float* __restrict__ ov)
{
    __shared__ float As[2][128 * GP2];
    __shared__ float Bs[2][128 * GP2];
    const int which = blockIdx.x >> 3;
    const int bx = blockIdx.x & 7;
    const float* A = (which == 0) ? Aq : (which == 1) ? Ak : Av;
    const float* W = (which == 0) ? Wq : (which == 1) ? Wk : Wv;
    float* out     = (which == 0) ? oq : (which == 1) ? ok : ov;
    const int mode = (which == 0) ? 0 : (which == 1) ? 2 : 3;
    gemm_body(A, W, out, mode, bx, blockIdx.y, &As[0][0], &Bs[0][0]);
}

__global__ __launch_bounds__(256, 2) void gemm_nt(
    const float* __restrict__ A, const float* __restrict__ W,
    float* __restrict__ out, int mode)
{
    __shared__ float As[2][128 * GP2];
    __shared__ float Bs[2][128 * GP2];
    gemm_body(A, W, out, mode, blockIdx.x, blockIdx.y, &As[0][0], &Bs[0][0]);
}

// ---------------------------------------------------------------------------
// Flash-style attention, exp/mask work covers V-fragment LDS latency.
// 256 threads, block = 128 q-rows of one (h,n), warp = 16 rows.
// ---------------------------------------------------------------------------
#define APAD 68
#define KV_FLOATS (64 * APAD)
#define BUF_FLOATS (2 * KV_FLOATS)
#define ATTN_SMEM (2 * BUF_FLOATS * (int)sizeof(float))

__global__ __launch_bounds__(256, 2) void attn(
    const float* __restrict__ gq, const float* __restrict__ gk,
    const float* __restrict__ gvt, const float* __restrict__ mask,
    float* __restrict__ go)
{
    extern __shared__ float smem[];
    const int tid  = threadIdx.x;
    const int lane = tid & 31, warp = tid >> 5;
    const int bh = blockIdx.y;
    const int q0 = blockIdx.x * 128;
    const size_t hb = (size_t)bh * (NQ * DH);

    uint32_t qa[8][4];
    {
        const float* qr0 = gq + hb + (size_t)(q0 + warp * 16 + (lane >> 2)) * DH;
        const float* qr1 = qr0 + 8 * DH;
#pragma unroll
        for (int kk = 0; kk < 8; kk++) {
            int c0 = kk * 8 + (lane & 3);
            qa[kk][0] = __float_as_uint(qr0[c0]);
            qa[kk][1] = __float_as_uint(qr1[c0]);
            qa[kk][2] = __float_as_uint(qr0[c0 + 4]);
            qa[kk][3] = __float_as_uint(qr1[c0 + 4]);
        }
    }

    float o[8][4];
#pragma unroll
    for (int et = 0; et < 8; et++)
#pragma unroll
        for (int i = 0; i < 4; i++) o[et][i] = 0.f;

    float Z0 = 0.f, Z1 = 0.f, S0 = 0.f, S1 = 0.f;

    const float* mbase = mask + (size_t)bh * ((size_t)NQ * NK)
                              + (size_t)(q0 + warp * 16 + (lane >> 2)) * NK;

    const int kb_off = ((lane >> 4) * 8 + (lane & 7)) * APAD + 4 * ((lane >> 3) & 1);

    const float* ksrc_b = gk + hb;
    const float* vsrc_b = gvt + hb;

    auto stage = [&](int kt, int b) {
        float* Kd = smem + b * BUF_FLOATS;
        float* Vd = Kd + KV_FLOATS;
        const float* ks = ksrc_b + (size_t)kt * 64 * DH;
        const float* vs = vsrc_b + kt * 64;
#pragma unroll
        for (int i = 0; i < 4; i++) {
            int cchunk = tid + i * 256;
            int row = cchunk >> 4, col = (cchunk & 15) * 4;
            cpa16(s2u(Kd + row * APAD + col), ks + row * 64 + col);
            cpa16(s2u(Vd + row * APAD + col), vs + (size_t)row * NK + col);
        }
        CPA_COMMIT;
    };

    if ((lane & 3) == 0) {
        const char* mp0 = (const char*)mbase;
        const char* mp1 = (const char*)(mbase + 8 * NK);
        pref_l2(mp0); pref_l2(mp0 + 128); pref_l2(mp1); pref_l2(mp1 + 128);
    }
    stage(0, 0);

    for (int kt = 0; kt < 16; kt++) {
        const int buf = kt & 1;
        CPA_WAIT0;
        __syncthreads();
        if (kt < 15) {
            stage(kt + 1, buf ^ 1);
            if ((lane & 3) == 0) {
                const char* mp0 = (const char*)(mbase + (kt + 1) * 64);
                const char* mp1 = (const char*)(mbase + (kt + 1) * 64 + 8 * NK);
                pref_l2(mp0); pref_l2(mp0 + 128); pref_l2(mp1); pref_l2(mp1 + 128);
            }
        }

        const float* Ks = smem + buf * BUF_FLOATS;
        const float* Vt = Ks + KV_FLOATS;

        // S = Q K^T : per kk issue all 4 K-fragment LDSMs, then 8 mmas
        float s[8][4];
#pragma unroll
        for (int nt = 0; nt < 8; nt++)
#pragma unroll
            for (int i = 0; i < 4; i++) s[nt][i] = 0.f;
#pragma unroll
        for (int kk = 0; kk < 8; kk++) {
            uint32_t bf[4][4];
#pragma unroll
            for (int ntp = 0; ntp < 4; ntp++)
                ldsm4(bf[ntp], s2u(Ks + kb_off + ntp * 16 * APAD + kk * 8));
#pragma unroll
            for (int ntp = 0; ntp < 4; ntp++) {
                mma8(s[ntp * 2 + 0], qa[kk], &bf[ntp][0]);
                mma8(s[ntp * 2 + 1], qa[kk], &bf[ntp][2]);
            }
        }

        // per slice: V LDSMs first, exp/mask (MUFU) covers their latency, then mmas
        const float2* mr0 = (const float2*)(mbase + kt * 64);
        const float2* mr1 = (const float2*)(mbase + kt * 64 + 8 * NK);
        float2 m0v[2], m1v[2];
        m0v[0] = mr0[lane & 3];       m1v[0] = mr1[lane & 3];
        m0v[1] = mr0[4 + (lane & 3)]; m1v[1] = mr1[4 + (lane & 3)];
#pragma unroll
        for (int kk = 0; kk < 8; kk++) {
            uint32_t bf[4][4];
#pragma unroll
            for (int etp = 0; etp < 4; etp++)
                ldsm4(bf[etp], s2u(Vt + kb_off + etp * 16 * APAD + kk * 8));

            float2 m0 = m0v[kk & 1], m1 = m1v[kk & 1];
            if (kk < 6) {
                m0v[kk & 1] = mr0[(kk + 2) * 4 + (lane & 3)];
                m1v[kk & 1] = mr1[(kk + 2) * 4 + (lane & 3)];
            }
            float p00 = __expf(s[kk][0]), p01 = __expf(s[kk][1]);
            float p10 = __expf(s[kk][2]), p11 = __expf(s[kk][3]);
            Z0 += p00 + p01; Z1 += p10 + p11;
            float pm00 = p00 * m0.x, pm01 = p01 * m0.y;
            float pm10 = p10 * m1.x, pm11 = p11 * m1.y;
            S0 += pm00 + pm01; S1 += pm10 + pm11;
            uint32_t pa[4];
            pa[0] = f2tf(pm00); pa[1] = f2tf(pm10);
            pa[2] = f2tf(pm01); pa[3] = f2tf(pm11);
#pragma unroll
            for (int etp = 0; etp < 4; etp++) {
                mma8(o[etp * 2 + 0], pa, &bf[etp][0]);
                mma8(o[etp * 2 + 1], pa, &bf[etp][2]);
            }
        }
    }

    Z0 += __shfl_xor_sync(0xffffffffu, Z0, 1); Z0 += __shfl_xor_sync(0xffffffffu, Z0, 2);
    Z1 += __shfl_xor_sync(0xffffffffu, Z1, 1); Z1 += __shfl_xor_sync(0xffffffffu, Z1, 2);
    S0 += __shfl_xor_sync(0xffffffffu, S0, 1); S0 += __shfl_xor_sync(0xffffffffu, S0, 2);
    S1 += __shfl_xor_sync(0xffffffffu, S1, 1); S1 += __shfl_xor_sync(0xffffffffu, S1, 2);

    float d0 = 1.f / (S0 + 1e-6f * Z0);
    float d1 = 1.f / (S1 + 1e-6f * Z1);

    const int n = bh & 7, h = bh >> 3;
    float* or0 = go + (size_t)(n * NQ + q0 + warp * 16 + (lane >> 2)) * DD + h * DH;
    float* or1 = or0 + 8 * DD;
#pragma unroll
    for (int et = 0; et < 8; et++) {
        int cc = et * 8 + 2 * (lane & 3);
        *(float2*)(or0 + cc) = make_float2(__uint_as_float(f2tf(o[et][0] * d0)),
                                           __uint_as_float(f2tf(o[et][1] * d0)));
        *(float2*)(or1 + cc) = make_float2(__uint_as_float(f2tf(o[et][2] * d1)),
                                           __uint_as_float(f2tf(o[et][3] * d1)));
    }
}

// ---------------------------------------------------------------------------
extern "C" void kernel_launch(void* const* d_in, const int* in_sizes, int n_in,
                              void* d_out, int out_size)
{
    const float* q    = (const float*)d_in[0];
    const float* k    = (const float*)d_in[1];
    const float* v    = (const float*)d_in[2];
    const float* mask = (const float*)d_in[3];
    const float* Wq   = (const float*)d_in[4];
    const float* Wk   = (const float*)d_in[5];
    const float* Wv   = (const float*)d_in[6];
    const float* Wo   = (const float*)d_in[7];
    float* out = (float*)d_out;

    float *pq, *pk, *pv, *po, *par, *pbr, *pcr, *pwr;
    cudaGetSymbolAddress((void**)&pq, g_q);
    cudaGetSymbolAddress((void**)&pk, g_k);
    cudaGetSymbolAddress((void**)&pv, g_v);
    cudaGetSymbolAddress((void**)&po, g_o);
    cudaGetSymbolAddress((void**)&par, g_ar);
    cudaGetSymbolAddress((void**)&pbr, g_br);
    cudaGetSymbolAddress((void**)&pcr, g_cr);
    cudaGetSymbolAddress((void**)&pwr, g_wr);

    cudaFuncSetAttribute(attn, cudaFuncAttributeMaxDynamicSharedMemorySize, ATTN_SMEM);

    round_all<<<1024, 256>>>((const float4*)q, (const float4*)k, (const float4*)v,
                             (const float4*)Wq, (const float4*)Wk, (const float4*)Wv,
                             (const float4*)Wo,
                             (float4*)par, (float4*)pbr, (float4*)pcr, (float4*)pwr);

    gemm_qkv<<<dim3(24, 64), 256>>>(par, pbr, pcr,
                                    pwr + 0 * DD * DD, pwr + 1 * DD * DD, pwr + 2 * DD * DD,
                                    pq, pk, pv);
    attn<<<dim3(8, 128), 256, ATTN_SMEM>>>(pq, pk, pv, mask, po);
    gemm_nt<<<dim3(8, 64), 256>>>(po, pwr + 3 * DD * DD, out, 1);
}